// round 14
// baseline (speedup 1.0000x reference)
#include <cuda_runtime.h>
#include <cuda_fp16.h>
#include <cstdint>
#include <math.h>

// ---------------- problem constants ----------------
#define B_IMG  32
#define C_IN   256
#define HWDIM  56
#define PIX_PER_IMG (HWDIM*HWDIM)      // 3136
#define NPIX   (B_IMG*PIX_PER_IMG)     // 100352
#define N_TOK  49
#define NH     8
#define DH     32
#define DE     1024
#define NWIN   (B_IMG*64)              // 2048
#define QSCALE 0.17677669529663687f
#define MT_TOT (NPIX/16)               // 6272

// ---------------- scratch ----------------
__device__ float g_ln2m[NPIX];
__device__ float g_ln2r[NPIX];
__device__ float g_q[NWIN*NH*N_TOK*DH];
__device__ float g_k[NWIN*NH*N_TOK*DH];
__device__ float g_v[(size_t)NPIX*DE];         // RASTER rows: [pixel][1024]

// fragment-layout fp16 buffers
__device__ uint4 g_a1[(size_t)MT_TOT*16*32];   // [mt][kt16][lane]
__device__ uint4 g_b1p[192*8*32];              // [nt][kc32][lane] kt-paired
__device__ uint4 g_a2[(size_t)MT_TOT*64*32];   // [mt][kt64][lane]
__device__ uint4 g_b2p[32*32*32];              // [nt][kc32][lane] kt-paired

__device__ __forceinline__ float gelu_exact(float x) {
    return 0.5f * x * (1.0f + erff(x * 0.7071067811865476f));
}

// ---------------- mma helpers ----------------
__device__ __forceinline__ void mma16816(float* c, const uint32_t* a, const uint32_t* b) {
    asm volatile("mma.sync.aligned.m16n8k16.row.col.f32.f16.f16.f32 "
        "{%0,%1,%2,%3}, {%4,%5,%6,%7}, {%8,%9}, {%0,%1,%2,%3};"
        : "+f"(c[0]), "+f"(c[1]), "+f"(c[2]), "+f"(c[3])
        : "r"(a[0]), "r"(a[1]), "r"(a[2]), "r"(a[3]), "r"(b[0]), "r"(b[1]));
}
__device__ __forceinline__ uint32_t packh2(__half a, __half b) {
    __half2 t = __halves2half2(a, b);
    return *reinterpret_cast<uint32_t*>(&t);
}
__device__ __forceinline__ uint32_t roundh2(float v0, float v1) {
    return packh2(__float2half_rn(v0), __float2half_rn(v1));
}

// smem layout (dynamic): A double buffer 8KB; epilogue staging reuses (16.6KB)
//  As (uint4): [stage2][kt2][mt4][lane32]
#define AS_IDX(s,kt,mt)  ((((s)*2+(kt))*4+(mt))*32)
#define SMEM_BYTES 16896

// ================= converters =================
__global__ __launch_bounds__(256) void conv_w1(const float* __restrict__ qk_w,
                                               const float* __restrict__ v_w) {
    int t = blockIdx.x * 256 + threadIdx.x;     // 0..49151
    int lane = t & 31;
    int kc = (t >> 5) & 7;
    int nt = t >> 8;
    int n = nt * 8 + (lane >> 2);
    int k = kc * 32 + (lane & 3) * 2;
    const float* wr = (n < 512) ? qk_w + (size_t)n * 256 : v_w + (size_t)(n - 512) * 256;
    uint4 o;
    o.x = roundh2(wr[k],      wr[k + 1]);
    o.y = roundh2(wr[k + 8],  wr[k + 9]);
    o.z = roundh2(wr[k + 16], wr[k + 17]);
    o.w = roundh2(wr[k + 24], wr[k + 25]);
    g_b1p[t] = o;
}

__global__ __launch_bounds__(256) void conv_w2(const float* __restrict__ proj_w) {
    int t = blockIdx.x * 256 + threadIdx.x;     // 0..32767
    int lane = t & 31;
    int kc = (t >> 5) & 31;
    int nt = t >> 10;
    int n = nt * 8 + (lane >> 2);
    int k = kc * 32 + (lane & 3) * 2;
    const float* wr = proj_w + (size_t)n * 1024;
    uint4 o;
    o.x = roundh2(wr[k],      wr[k + 1]);
    o.y = roundh2(wr[k + 8],  wr[k + 9]);
    o.z = roundh2(wr[k + 16], wr[k + 17]);
    o.w = roundh2(wr[k + 24], wr[k + 25]);
    g_b2p[t] = o;
}

// ================= conv_a1: x -> LN (stats in-block) -> A1 frags (fp16) =================
__global__ __launch_bounds__(256) void conv_a1(const float* __restrict__ x,
                                               const float* __restrict__ pre_g,
                                               const float* __restrict__ pre_b) {
    int mt = blockIdx.x;
    int w = threadIdx.x >> 5, lane = threadIdx.x & 31;
    int rl0 = lane >> 2, rl1 = rl0 + 8;
    int r0 = mt * 16 + rl0, r1 = r0 + 8;
    int img = r0 / PIX_PER_IMG;
    int hw0 = r0 - img * PIX_PER_IMG;
    int hw1 = hw0 + 8;
    const float* xb = x + (size_t)img * C_IN * PIX_PER_IMG;

    float v0[8], v1[8];
    #pragma unroll
    for (int kk = 0; kk < 2; kk++) {
        int kt = w + kk * 8;
        int c = kt * 16 + (lane & 3) * 2;
        #pragma unroll
        for (int p2 = 0; p2 < 2; p2++) {
            int cc = c + p2 * 8;
            int ib = kk * 4 + p2 * 2;
            v0[ib + 0] = xb[(size_t)cc * PIX_PER_IMG + hw0];
            v0[ib + 1] = xb[(size_t)(cc + 1) * PIX_PER_IMG + hw0];
            v1[ib + 0] = xb[(size_t)cc * PIX_PER_IMG + hw1];
            v1[ib + 1] = xb[(size_t)(cc + 1) * PIX_PER_IMG + hw1];
        }
    }

    float s0 = 0.f, ss0 = 0.f, s1 = 0.f, ss1 = 0.f;
    #pragma unroll
    for (int i = 0; i < 8; i++) {
        s0 += v0[i]; ss0 += v0[i] * v0[i];
        s1 += v1[i]; ss1 += v1[i] * v1[i];
    }
    #pragma unroll
    for (int off = 1; off <= 2; off <<= 1) {
        s0  += __shfl_xor_sync(0xffffffffu, s0, off);
        ss0 += __shfl_xor_sync(0xffffffffu, ss0, off);
        s1  += __shfl_xor_sync(0xffffffffu, s1, off);
        ss1 += __shfl_xor_sync(0xffffffffu, ss1, off);
    }
    __shared__ float shs[16][8], shss[16][8];
    if ((lane & 3) == 0) {
        shs[rl0][w] = s0;  shss[rl0][w] = ss0;
        shs[rl1][w] = s1;  shss[rl1][w] = ss1;
    }
    __syncthreads();
    float S0 = 0.f, SS0 = 0.f, S1 = 0.f, SS1 = 0.f;
    #pragma unroll
    for (int q = 0; q < 8; q++) {
        S0 += shs[rl0][q]; SS0 += shss[rl0][q];
        S1 += shs[rl1][q]; SS1 += shss[rl1][q];
    }
    float mu0 = S0 * (1.0f / 256.0f);
    float rs0 = rsqrtf(SS0 * (1.0f / 256.0f) - mu0 * mu0 + 1e-5f);
    float mu1 = S1 * (1.0f / 256.0f);
    float rs1 = rsqrtf(SS1 * (1.0f / 256.0f) - mu1 * mu1 + 1e-5f);

    #pragma unroll
    for (int kk = 0; kk < 2; kk++) {
        int kt = w + kk * 8;
        int c = kt * 16 + (lane & 3) * 2;
        uint4 hv;
        #pragma unroll
        for (int p2 = 0; p2 < 2; p2++) {
            int cc = c + p2 * 8;
            int ib = kk * 4 + p2 * 2;
            float g0 = pre_g[cc], b0 = pre_b[cc], g1 = pre_g[cc + 1], b1 = pre_b[cc + 1];
            float t00 = (v0[ib + 0] - mu0) * rs0 * g0 + b0;
            float t01 = (v0[ib + 1] - mu0) * rs0 * g1 + b1;
            float t10 = (v1[ib + 0] - mu1) * rs1 * g0 + b0;
            float t11 = (v1[ib + 1] - mu1) * rs1 * g1 + b1;
            (&hv.x)[2 * p2]     = roundh2(t00, t01);
            (&hv.x)[2 * p2 + 1] = roundh2(t10, t11);
        }
        g_a1[((size_t)mt * 16 + kt) * 32 + lane] = hv;
    }
}

// ================= conv_a2: gelu(postLN/id(g_v)) -> A2 frags (fp16) =================
__global__ __launch_bounds__(256) void conv_a2(const float* __restrict__ post_g,
                                               const float* __restrict__ post_b) {
    int mt = blockIdx.x;
    int w = threadIdx.x >> 5, lane = threadIdx.x & 31;
    int r0 = mt * 16 + (lane >> 2), r1 = r0 + 8;
    const float* gv0 = g_v + (size_t)r0 * DE;
    const float* gv1 = g_v + (size_t)r1 * DE;
    float mu0 = g_ln2m[r0], rs0 = g_ln2r[r0];
    float mu1 = g_ln2m[r1], rs1 = g_ln2r[r1];
    #pragma unroll
    for (int kk = 0; kk < 8; kk++) {
        int kt = w + kk * 8;
        int c = kt * 16 + (lane & 3) * 2;
        uint4 hv;
        #pragma unroll
        for (int p2 = 0; p2 < 2; p2++) {
            int cc = c + p2 * 8;
            float2 f0 = *(const float2*)(gv0 + cc);
            float2 f1 = *(const float2*)(gv1 + cc);
            float t00 = f0.x, t01 = f0.y, t10 = f1.x, t11 = f1.y;
            if (cc < 512) {
                float g0 = post_g[cc], b0 = post_b[cc];
                float g1 = post_g[cc + 1], b1 = post_b[cc + 1];
                t00 = (t00 - mu0) * rs0 * g0 + b0;
                t01 = (t01 - mu0) * rs0 * g1 + b1;
                t10 = (t10 - mu1) * rs1 * g0 + b0;
                t11 = (t11 - mu1) * rs1 * g1 + b1;
            }
            t00 = gelu_exact(t00); t01 = gelu_exact(t01);
            t10 = gelu_exact(t10); t11 = gelu_exact(t11);
            (&hv.x)[2 * p2]     = roundh2(t00, t01);
            (&hv.x)[2 * p2 + 1] = roundh2(t10, t11);
        }
        g_a2[((size_t)mt * 64 + kt) * 32 + lane] = hv;
    }
}

// ================= GEMM1: CTA 64x128 (128 thr, 3 CTAs/SM), B reg-double-buffered =================
__global__ __launch_bounds__(128, 3) void gemm1_mma(
    const float* __restrict__ qk_b, const float* __restrict__ v_b)
{
    extern __shared__ char smem[];
    uint4* As = (uint4*)smem;

    const int tid = threadIdx.x, lane = tid & 31, wid = tid >> 5;
    const int wm = wid >> 1, wn = wid & 1;
    const int mb = blockIdx.y * 64, nb = blockIdx.x * 128;
    const int mtg0 = mb >> 4, ntg0 = nb >> 3;

    float acc[2][8][4];
    #pragma unroll
    for (int i = 0; i < 2; i++)
        #pragma unroll
        for (int j = 0; j < 8; j++)
            #pragma unroll
            for (int r = 0; r < 4; r++) acc[i][j][r] = 0.f;

    uint4 av[2];
    uint4 bqA[8], bqB[8];

#define G1_LOADA(KC) { \
    _Pragma("unroll") \
    for (int j = 0; j < 2; j++) { \
        int i = tid + j * 128; \
        int l = i & 31, mt = (i >> 5) & 3, ktl = i >> 7; \
        av[j] = g_a1[((size_t)(mtg0 + mt) * 16 + (KC) * 2 + ktl) * 32 + l]; \
    } }

#define G_STOREA(ST) { \
    _Pragma("unroll") \
    for (int j = 0; j < 2; j++) { \
        int i = tid + j * 128; \
        int l = i & 31, mt = (i >> 5) & 3, ktl = i >> 7; \
        As[AS_IDX(ST, ktl, mt) + l] = av[j]; \
    } }

#define G1_LOADB(BQ, KC) { \
    _Pragma("unroll") \
    for (int nti = 0; nti < 8; nti++) \
        BQ[nti] = g_b1p[((size_t)(ntg0 + wn * 8 + nti) * 8 + (KC)) * 32 + lane]; }

#define G_COMPUTE(BUF, BQ) { \
    _Pragma("unroll") \
    for (int kt = 0; kt < 2; kt++) { \
        uint32_t ah[2][4]; \
        _Pragma("unroll") \
        for (int mti = 0; mti < 2; mti++) \
            *(uint4*)ah[mti] = As[AS_IDX(BUF, kt, wm * 2 + mti) + lane]; \
        _Pragma("unroll") \
        for (int mti = 0; mti < 2; mti++) \
            _Pragma("unroll") \
            for (int nti = 0; nti < 8; nti++) { \
                uint32_t bb[2] = { (&BQ[nti].x)[2 * kt], (&BQ[nti].x)[2 * kt + 1] }; \
                mma16816(acc[mti][nti], ah[mti], bb); \
            } \
    } }

    G1_LOADB(bqA, 0);
    G1_LOADA(0); G_STOREA(0);
    __syncthreads();

    const int NCH = 8;   // even
    for (int kc2 = 0; kc2 < NCH; kc2 += 2) {
        // phase 0: compute kc2 (buf kc2&1) with bqA; prefetch kc2+1 -> bqB
        {
            int buf = kc2 & 1;
            if (kc2 + 1 < NCH) { G1_LOADA(kc2 + 1); G1_LOADB(bqB, kc2 + 1); }
            G_COMPUTE(buf, bqA);
            if (kc2 + 1 < NCH) { G_STOREA(buf ^ 1); }
            __syncthreads();
        }
        // phase 1: compute kc2+1 with bqB; prefetch kc2+2 -> bqA
        if (kc2 + 1 < NCH) {
            int buf = (kc2 + 1) & 1;
            if (kc2 + 2 < NCH) { G1_LOADA(kc2 + 2); G1_LOADB(bqA, kc2 + 2); }
            G_COMPUTE(buf, bqB);
            if (kc2 + 2 < NCH) { G_STOREA(buf ^ 1); }
            __syncthreads();
        }
    }

    // ---- epilogue: stage 64x64 halves, scatter q/k/v ----
    float* stg = (float*)smem;
    for (int h = 0; h < 2; h++) {
        if (wn == h) {
            #pragma unroll
            for (int mti = 0; mti < 2; mti++)
                #pragma unroll
                for (int nti = 0; nti < 8; nti++) {
                    int r0 = wm * 32 + mti * 16 + (lane >> 2);
                    int c0 = nti * 8 + (lane & 3) * 2;
                    stg[r0 * 65 + c0]       = acc[mti][nti][0];
                    stg[r0 * 65 + c0 + 1]   = acc[mti][nti][1];
                    stg[(r0 + 8) * 65 + c0]     = acc[mti][nti][2];
                    stg[(r0 + 8) * 65 + c0 + 1] = acc[mti][nti][3];
                }
        }
        __syncthreads();
        int cc = tid & 63, qr = tid >> 6;
        int o = nb + h * 64 + cc;
        float bias = (o < 512) ? qk_b[o] : v_b[o - 512];
        #pragma unroll 4
        for (int i = 0; i < 32; i++) {
            int ml = qr + i * 2;
            float val = stg[ml * 65 + cc] + bias;
            int m = mb + ml;
            if (o < 512) {
                int bimg = m / PIX_PER_IMG;
                int hw = m - bimg * PIX_PER_IMG;
                int hh = hw / HWDIM, ww = hw - hh * HWDIM;
                int wi = bimg * 64 + (hh & 7) * 8 + (ww & 7);
                int n  = (hh >> 3) * 7 + (ww >> 3);
                if (o < 256)
                    g_q[(((size_t)wi * 8 + (o >> 5)) * 49 + n) * 32 + (o & 31)] = val * QSCALE;
                else {
                    int q2 = o - 256;
                    g_k[(((size_t)wi * 8 + (q2 >> 5)) * 49 + n) * 32 + (q2 & 31)] = val;
                }
            } else {
                g_v[(size_t)m * DE + (o - 512)] = val;
            }
        }
        __syncthreads();
    }
#undef G1_LOADA
#undef G1_LOADB
}

// ================= attention: one CTA per (window, head) =================
__global__ __launch_bounds__(128) void attn_kernel(const float* __restrict__ rpb) {
    int head = blockIdx.x;
    int wi   = blockIdx.y;
    int wp   = wi & 63;
    int bimg = wi >> 6;
    int tid  = threadIdx.x;

    __shared__ float Qs[49][33];
    __shared__ float Ks[49][33];
    __shared__ float Vs[49][64];
    __shared__ float Ss[49 * 49];
    __shared__ float rpbs[169];

    const float* qbase = g_q + ((size_t)wi * 8 + head) * 49 * 32;
    const float* kbase = g_k + ((size_t)wi * 8 + head) * 49 * 32;

    for (int i = tid; i < 49 * 32; i += 128) {
        Qs[i >> 5][i & 31] = qbase[i];
        Ks[i >> 5][i & 31] = kbase[i];
    }
    for (int i = tid; i < 169; i += 128)
        rpbs[i] = rpb[((size_t)wp * 169 + i) * 8 + head];
    for (int i = tid; i < 49 * 64; i += 128) {
        int n = i >> 6, vh = i & 63;
        int hh = (n / 7) * 8 + (wp >> 3), ww = (n % 7) * 8 + (wp & 7);
        size_t pix = (size_t)bimg * PIX_PER_IMG + hh * HWDIM + ww;
        Vs[n][vh] = g_v[pix * DE + head * 64 + vh];
    }
    __syncthreads();

    for (int i = tid; i < 49 * 49; i += 128) {
        int n = i / 49, m = i % 49;
        float s = 0.f;
        #pragma unroll
        for (int d = 0; d < 32; d++) s += Qs[n][d] * Ks[m][d];
        int i1 = n / 7, j1 = n % 7, i2 = m / 7, j2 = m % 7;
        s += rpbs[(i1 - i2 + 6) * 13 + (j1 - j2 + 6)];
        Ss[i] = s;
    }
    __syncthreads();

    if (tid < 49) {
        float* row = Ss + tid * 49;
        float mx = -1e30f;
        #pragma unroll 7
        for (int m = 0; m < 49; m++) mx = fmaxf(mx, row[m]);
        float sum = 0.f;
        #pragma unroll 7
        for (int m = 0; m < 49; m++) { float e = __expf(row[m] - mx); row[m] = e; sum += e; }
        float inv = 1.0f / sum;
        #pragma unroll 7
        for (int m = 0; m < 49; m++) row[m] *= inv;
    }
    __syncthreads();

    for (int i = tid; i < 49 * 64; i += 128) {
        int n = i >> 6, vh = i & 63;
        float o = 0.f;
        #pragma unroll 7
        for (int m = 0; m < 49; m++) o += Ss[n * 49 + m] * Vs[m][vh];
        int hh = (n / 7) * 8 + (wp >> 3), ww = (n % 7) * 8 + (wp & 7);
        size_t pix = (size_t)bimg * PIX_PER_IMG + hh * HWDIM + ww;
        g_v[pix * DE + head * 64 + vh] = o;
    }
}

// ================= post-LN stats over first 512 cols of g_v =================
__global__ __launch_bounds__(256) void ln2_stats_kernel() {
    int row = blockIdx.x * 8 + (threadIdx.x >> 5);
    int lane = threadIdx.x & 31;
    const float4* p = (const float4*)(g_v + (size_t)row * DE);
    float s = 0.f, ss = 0.f;
    #pragma unroll
    for (int j = 0; j < 4; j++) {
        float4 v = p[lane + 32 * j];
        s  += v.x + v.y + v.z + v.w;
        ss += v.x * v.x + v.y * v.y + v.z * v.z + v.w * v.w;
    }
    #pragma unroll
    for (int off = 16; off; off >>= 1) {
        s  += __shfl_down_sync(0xffffffffu, s, off);
        ss += __shfl_down_sync(0xffffffffu, ss, off);
    }
    if (lane == 0) {
        float mean = s * (1.0f / 512.0f);
        float var  = ss * (1.0f / 512.0f) - mean * mean;
        g_ln2m[row] = mean;
        g_ln2r[row] = rsqrtf(var + 1e-5f);
    }
}

// ================= GEMM2: CTA 64x128 (128 thr, 3 CTAs/SM), B reg-double-buffered =================
__global__ __launch_bounds__(128, 3) void gemm2_mma(
    const float* __restrict__ x,
    const float* __restrict__ proj_b,
    float* __restrict__ out)
{
    extern __shared__ char smem[];
    uint4* As = (uint4*)smem;

    const int tid = threadIdx.x, lane = tid & 31, wid = tid >> 5;
    const int wm = wid >> 1, wn = wid & 1;
    const int mb = blockIdx.x * 64, nb = blockIdx.y * 128;
    const int mtg0 = mb >> 4, ntg0 = nb >> 3;

    float acc[2][8][4];
    #pragma unroll
    for (int i = 0; i < 2; i++)
        #pragma unroll
        for (int j = 0; j < 8; j++)
            #pragma unroll
            for (int r = 0; r < 4; r++) acc[i][j][r] = 0.f;

    uint4 av[2];
    uint4 bqA[8], bqB[8];

#define G2_LOADA(KC) { \
    _Pragma("unroll") \
    for (int j = 0; j < 2; j++) { \
        int i = tid + j * 128; \
        int l = i & 31, mt = (i >> 5) & 3, ktl = i >> 7; \
        av[j] = g_a2[((size_t)(mtg0 + mt) * 64 + (KC) * 2 + ktl) * 32 + l]; \
    } }

#define G2_LOADB(BQ, KC) { \
    _Pragma("unroll") \
    for (int nti = 0; nti < 8; nti++) \
        BQ[nti] = g_b2p[((size_t)(ntg0 + wn * 8 + nti) * 32 + (KC)) * 32 + lane]; }

    G2_LOADB(bqA, 0);
    G2_LOADA(0); G_STOREA(0);
    __syncthreads();

    const int NCH = 32;  // even
    for (int kc2 = 0; kc2 < NCH; kc2 += 2) {
        {
            int buf = kc2 & 1;
            if (kc2 + 1 < NCH) { G2_LOADA(kc2 + 1); G2_LOADB(bqB, kc2 + 1); }
            G_COMPUTE(buf, bqA);
            if (kc2 + 1 < NCH) { G_STOREA(buf ^ 1); }
            __syncthreads();
        }
        if (kc2 + 1 < NCH) {
            int buf = (kc2 + 1) & 1;
            if (kc2 + 2 < NCH) { G2_LOADA(kc2 + 2); G2_LOADB(bqA, kc2 + 2); }
            G_COMPUTE(buf, bqB);
            if (kc2 + 2 < NCH) { G_STOREA(buf ^ 1); }
            __syncthreads();
        }
    }

    // ---- epilogue: +bias +residual, rolled coalesced writes ----
    float* stg = (float*)smem;
    const int ml = tid & 63;
    const int cq = tid >> 6;   // 0..1
    int m = mb + ml;
    int bimg = m / PIX_PER_IMG;
    int hw = m - bimg * PIX_PER_IMG;
    int hh = hw / HWDIM, ww = hw - hh * HWDIM;
    int h2 = hh + 2; if (h2 >= HWDIM) h2 -= HWDIM;
    int w2 = ww + 2; if (w2 >= HWDIM) w2 -= HWDIM;
    size_t inbase  = (size_t)bimg * C_IN * PIX_PER_IMG + hw;
    size_t outbase = (size_t)bimg * C_IN * PIX_PER_IMG + h2 * HWDIM + w2;

    for (int h = 0; h < 2; h++) {
        if (wn == h) {
            #pragma unroll
            for (int mti = 0; mti < 2; mti++)
                #pragma unroll
                for (int nti = 0; nti < 8; nti++) {
                    int r0 = wm * 32 + mti * 16 + (lane >> 2);
                    int c0 = nti * 8 + (lane & 3) * 2;
                    stg[r0 * 65 + c0]       = acc[mti][nti][0];
                    stg[r0 * 65 + c0 + 1]   = acc[mti][nti][1];
                    stg[(r0 + 8) * 65 + c0]     = acc[mti][nti][2];
                    stg[(r0 + 8) * 65 + c0 + 1] = acc[mti][nti][3];
                }
        }
        __syncthreads();
        #pragma unroll 4
        for (int i = 0; i < 32; i++) {
            int c = i * 2 + cq;
            int o = nb + h * 64 + c;
            float val = stg[ml * 65 + c] + proj_b[o] + x[inbase + (size_t)o * PIX_PER_IMG];
            out[outbase + (size_t)o * PIX_PER_IMG] = val;
        }
        __syncthreads();
    }
#undef G2_LOADA
#undef G2_LOADB
}

// ================= launch =================
extern "C" void kernel_launch(void* const* d_in, const int* in_sizes, int n_in,
                              void* d_out, int out_size) {
    const float* x      = (const float*)d_in[0];
    const float* pre_g  = (const float*)d_in[1];
    const float* pre_b  = (const float*)d_in[2];
    const float* post_g = (const float*)d_in[3];
    const float* post_b = (const float*)d_in[4];
    const float* qk_w   = (const float*)d_in[5];
    const float* qk_b   = (const float*)d_in[6];
    const float* v_w    = (const float*)d_in[7];
    const float* v_b    = (const float*)d_in[8];
    const float* proj_w = (const float*)d_in[9];
    const float* proj_b = (const float*)d_in[10];
    const float* rpb    = (const float*)d_in[11];
    float* out = (float*)d_out;

    static int configured = 0;
    if (!configured) {
        cudaFuncSetAttribute(gemm1_mma, cudaFuncAttributeMaxDynamicSharedMemorySize, SMEM_BYTES);
        cudaFuncSetAttribute(gemm2_mma, cudaFuncAttributeMaxDynamicSharedMemorySize, SMEM_BYTES);
        configured = 1;
    }

    conv_w1<<<192, 256>>>(qk_w, v_w);
    conv_w2<<<128, 256>>>(proj_w);
    conv_a1<<<MT_TOT, 256>>>(x, pre_g, pre_b);
    gemm1_mma<<<dim3(12, NPIX / 64), 128, SMEM_BYTES>>>(qk_b, v_b);
    attn_kernel<<<dim3(NH, NWIN), 128>>>(rpb);
    ln2_stats_kernel<<<NPIX / 8, 256>>>();
    conv_a2<<<MT_TOT, 256>>>(post_g, post_b);
    gemm2_mma<<<dim3(NPIX / 64, 2), 128, SMEM_BYTES>>>(x, proj_b, out);
}

// round 15
// speedup vs baseline: 1.1616x; 1.1616x over previous
#include <cuda_runtime.h>
#include <cuda_fp16.h>
#include <cstdint>
#include <math.h>

// ---------------- problem constants ----------------
#define B_IMG  32
#define C_IN   256
#define HWDIM  56
#define PIX_PER_IMG (HWDIM*HWDIM)      // 3136
#define NPIX   (B_IMG*PIX_PER_IMG)     // 100352
#define N_TOK  49
#define NH     8
#define DH     32
#define DE     1024
#define NWIN   (B_IMG*64)              // 2048
#define QSCALE 0.17677669529663687f
#define MT_TOT (NPIX/16)               // 6272

// ---------------- scratch ----------------
__device__ float g_ln2m[NPIX];
__device__ float g_ln2r[NPIX];
__device__ float g_q[NWIN*NH*N_TOK*DH];
__device__ float g_k[NWIN*NH*N_TOK*DH];
__device__ float g_v[(size_t)NPIX*DE];         // RASTER rows: [pixel][1024]

// fragment-layout fp16 buffers
__device__ uint4 g_a1[(size_t)MT_TOT*16*32];   // [mt][kt16][lane]
__device__ uint4 g_b1p[192*8*32];              // [nt][kc32][lane] kt-paired
__device__ uint4 g_a2[(size_t)MT_TOT*64*32];   // [mt][kt64][lane]
__device__ uint4 g_b2p[32*32*32];              // [nt][kc32][lane] kt-paired

__device__ __forceinline__ float gelu_exact(float x) {
    return 0.5f * x * (1.0f + erff(x * 0.7071067811865476f));
}

// ---------------- mma helpers ----------------
__device__ __forceinline__ void mma16816(float* c, const uint32_t* a, const uint32_t* b) {
    asm volatile("mma.sync.aligned.m16n8k16.row.col.f32.f16.f16.f32 "
        "{%0,%1,%2,%3}, {%4,%5,%6,%7}, {%8,%9}, {%0,%1,%2,%3};"
        : "+f"(c[0]), "+f"(c[1]), "+f"(c[2]), "+f"(c[3])
        : "r"(a[0]), "r"(a[1]), "r"(a[2]), "r"(a[3]), "r"(b[0]), "r"(b[1]));
}
__device__ __forceinline__ uint32_t packh2(__half a, __half b) {
    __half2 t = __halves2half2(a, b);
    return *reinterpret_cast<uint32_t*>(&t);
}
__device__ __forceinline__ uint32_t roundh2(float v0, float v1) {
    return packh2(__float2half_rn(v0), __float2half_rn(v1));
}

// smem layout (dynamic): A double buffer 8KB; epilogue staging reuses (16.6KB)
//  As (uint4): [stage2][kt2][mt4][lane32]
#define AS_IDX(s,kt,mt)  ((((s)*2+(kt))*4+(mt))*32)
#define SMEM_BYTES 16896

// ================= converters =================
__global__ __launch_bounds__(256) void conv_w1(const float* __restrict__ qk_w,
                                               const float* __restrict__ v_w) {
    int t = blockIdx.x * 256 + threadIdx.x;     // 0..49151
    int lane = t & 31;
    int kc = (t >> 5) & 7;
    int nt = t >> 8;
    int n = nt * 8 + (lane >> 2);
    int k = kc * 32 + (lane & 3) * 2;
    const float* wr = (n < 512) ? qk_w + (size_t)n * 256 : v_w + (size_t)(n - 512) * 256;
    uint4 o;
    o.x = roundh2(wr[k],      wr[k + 1]);
    o.y = roundh2(wr[k + 8],  wr[k + 9]);
    o.z = roundh2(wr[k + 16], wr[k + 17]);
    o.w = roundh2(wr[k + 24], wr[k + 25]);
    g_b1p[t] = o;
}

__global__ __launch_bounds__(256) void conv_w2(const float* __restrict__ proj_w) {
    int t = blockIdx.x * 256 + threadIdx.x;     // 0..32767
    int lane = t & 31;
    int kc = (t >> 5) & 31;
    int nt = t >> 10;
    int n = nt * 8 + (lane >> 2);
    int k = kc * 32 + (lane & 3) * 2;
    const float* wr = proj_w + (size_t)n * 1024;
    uint4 o;
    o.x = roundh2(wr[k],      wr[k + 1]);
    o.y = roundh2(wr[k + 8],  wr[k + 9]);
    o.z = roundh2(wr[k + 16], wr[k + 17]);
    o.w = roundh2(wr[k + 24], wr[k + 25]);
    g_b2p[t] = o;
}

// ================= conv_a1: x -> LN (stats in-block) -> A1 frags (fp16) =================
__global__ __launch_bounds__(256) void conv_a1(const float* __restrict__ x,
                                               const float* __restrict__ pre_g,
                                               const float* __restrict__ pre_b) {
    int mt = blockIdx.x;
    int w = threadIdx.x >> 5, lane = threadIdx.x & 31;
    int rl0 = lane >> 2, rl1 = rl0 + 8;
    int r0 = mt * 16 + rl0, r1 = r0 + 8;
    int img = r0 / PIX_PER_IMG;
    int hw0 = r0 - img * PIX_PER_IMG;
    int hw1 = hw0 + 8;
    const float* xb = x + (size_t)img * C_IN * PIX_PER_IMG;

    float v0[8], v1[8];
    #pragma unroll
    for (int kk = 0; kk < 2; kk++) {
        int kt = w + kk * 8;
        int c = kt * 16 + (lane & 3) * 2;
        #pragma unroll
        for (int p2 = 0; p2 < 2; p2++) {
            int cc = c + p2 * 8;
            int ib = kk * 4 + p2 * 2;
            v0[ib + 0] = xb[(size_t)cc * PIX_PER_IMG + hw0];
            v0[ib + 1] = xb[(size_t)(cc + 1) * PIX_PER_IMG + hw0];
            v1[ib + 0] = xb[(size_t)cc * PIX_PER_IMG + hw1];
            v1[ib + 1] = xb[(size_t)(cc + 1) * PIX_PER_IMG + hw1];
        }
    }

    float s0 = 0.f, ss0 = 0.f, s1 = 0.f, ss1 = 0.f;
    #pragma unroll
    for (int i = 0; i < 8; i++) {
        s0 += v0[i]; ss0 += v0[i] * v0[i];
        s1 += v1[i]; ss1 += v1[i] * v1[i];
    }
    #pragma unroll
    for (int off = 1; off <= 2; off <<= 1) {
        s0  += __shfl_xor_sync(0xffffffffu, s0, off);
        ss0 += __shfl_xor_sync(0xffffffffu, ss0, off);
        s1  += __shfl_xor_sync(0xffffffffu, s1, off);
        ss1 += __shfl_xor_sync(0xffffffffu, ss1, off);
    }
    __shared__ float shs[16][8], shss[16][8];
    if ((lane & 3) == 0) {
        shs[rl0][w] = s0;  shss[rl0][w] = ss0;
        shs[rl1][w] = s1;  shss[rl1][w] = ss1;
    }
    __syncthreads();
    float S0 = 0.f, SS0 = 0.f, S1 = 0.f, SS1 = 0.f;
    #pragma unroll
    for (int q = 0; q < 8; q++) {
        S0 += shs[rl0][q]; SS0 += shss[rl0][q];
        S1 += shs[rl1][q]; SS1 += shss[rl1][q];
    }
    float mu0 = S0 * (1.0f / 256.0f);
    float rs0 = rsqrtf(SS0 * (1.0f / 256.0f) - mu0 * mu0 + 1e-5f);
    float mu1 = S1 * (1.0f / 256.0f);
    float rs1 = rsqrtf(SS1 * (1.0f / 256.0f) - mu1 * mu1 + 1e-5f);

    #pragma unroll
    for (int kk = 0; kk < 2; kk++) {
        int kt = w + kk * 8;
        int c = kt * 16 + (lane & 3) * 2;
        uint4 hv;
        #pragma unroll
        for (int p2 = 0; p2 < 2; p2++) {
            int cc = c + p2 * 8;
            int ib = kk * 4 + p2 * 2;
            float g0 = pre_g[cc], b0 = pre_b[cc], g1 = pre_g[cc + 1], b1 = pre_b[cc + 1];
            float t00 = (v0[ib + 0] - mu0) * rs0 * g0 + b0;
            float t01 = (v0[ib + 1] - mu0) * rs0 * g1 + b1;
            float t10 = (v1[ib + 0] - mu1) * rs1 * g0 + b0;
            float t11 = (v1[ib + 1] - mu1) * rs1 * g1 + b1;
            (&hv.x)[2 * p2]     = roundh2(t00, t01);
            (&hv.x)[2 * p2 + 1] = roundh2(t10, t11);
        }
        g_a1[((size_t)mt * 16 + kt) * 32 + lane] = hv;
    }
}

// ================= conv_a2: gelu(postLN/id(g_v)) -> A2 frags (fp16) =================
__global__ __launch_bounds__(256) void conv_a2(const float* __restrict__ post_g,
                                               const float* __restrict__ post_b) {
    int mt = blockIdx.x;
    int w = threadIdx.x >> 5, lane = threadIdx.x & 31;
    int r0 = mt * 16 + (lane >> 2), r1 = r0 + 8;
    const float* gv0 = g_v + (size_t)r0 * DE;
    const float* gv1 = g_v + (size_t)r1 * DE;
    float mu0 = g_ln2m[r0], rs0 = g_ln2r[r0];
    float mu1 = g_ln2m[r1], rs1 = g_ln2r[r1];
    #pragma unroll
    for (int kk = 0; kk < 8; kk++) {
        int kt = w + kk * 8;
        int c = kt * 16 + (lane & 3) * 2;
        uint4 hv;
        #pragma unroll
        for (int p2 = 0; p2 < 2; p2++) {
            int cc = c + p2 * 8;
            float2 f0 = *(const float2*)(gv0 + cc);
            float2 f1 = *(const float2*)(gv1 + cc);
            float t00 = f0.x, t01 = f0.y, t10 = f1.x, t11 = f1.y;
            if (cc < 512) {
                float g0 = post_g[cc], b0 = post_b[cc];
                float g1 = post_g[cc + 1], b1 = post_b[cc + 1];
                t00 = (t00 - mu0) * rs0 * g0 + b0;
                t01 = (t01 - mu0) * rs0 * g1 + b1;
                t10 = (t10 - mu1) * rs1 * g0 + b0;
                t11 = (t11 - mu1) * rs1 * g1 + b1;
            }
            t00 = gelu_exact(t00); t01 = gelu_exact(t01);
            t10 = gelu_exact(t10); t11 = gelu_exact(t11);
            (&hv.x)[2 * p2]     = roundh2(t00, t01);
            (&hv.x)[2 * p2 + 1] = roundh2(t10, t11);
        }
        g_a2[((size_t)mt * 64 + kt) * 32 + lane] = hv;
    }
}

// ================= GEMM1: CTA 64x128 (128 thr, 4 CTAs/SM), B direct =================
__global__ __launch_bounds__(128, 4) void gemm1_mma(
    const float* __restrict__ qk_b, const float* __restrict__ v_b)
{
    extern __shared__ char smem[];
    uint4* As = (uint4*)smem;

    const int tid = threadIdx.x, lane = tid & 31, wid = tid >> 5;
    const int wm = wid >> 1, wn = wid & 1;
    const int mb = blockIdx.y * 64, nb = blockIdx.x * 128;
    const int mtg0 = mb >> 4, ntg0 = nb >> 3;

    float acc[2][8][4];
    #pragma unroll
    for (int i = 0; i < 2; i++)
        #pragma unroll
        for (int j = 0; j < 8; j++)
            #pragma unroll
            for (int r = 0; r < 4; r++) acc[i][j][r] = 0.f;

    uint4 av[2];

#define G1_LOADA(KC) { \
    _Pragma("unroll") \
    for (int j = 0; j < 2; j++) { \
        int i = tid + j * 128; \
        int l = i & 31, mt = (i >> 5) & 3, ktl = i >> 7; \
        av[j] = g_a1[((size_t)(mtg0 + mt) * 16 + (KC) * 2 + ktl) * 32 + l]; \
    } }

#define G_STOREA(ST) { \
    _Pragma("unroll") \
    for (int j = 0; j < 2; j++) { \
        int i = tid + j * 128; \
        int l = i & 31, mt = (i >> 5) & 3, ktl = i >> 7; \
        As[AS_IDX(ST, ktl, mt) + l] = av[j]; \
    } }

#define G1_COMPUTE(BUF, KC) { \
    uint4 bq[8]; \
    _Pragma("unroll") \
    for (int nti = 0; nti < 8; nti++) \
        bq[nti] = g_b1p[((size_t)(ntg0 + wn * 8 + nti) * 8 + (KC)) * 32 + lane]; \
    _Pragma("unroll") \
    for (int kt = 0; kt < 2; kt++) { \
        uint32_t ah[2][4]; \
        _Pragma("unroll") \
        for (int mti = 0; mti < 2; mti++) \
            *(uint4*)ah[mti] = As[AS_IDX(BUF, kt, wm * 2 + mti) + lane]; \
        _Pragma("unroll") \
        for (int mti = 0; mti < 2; mti++) \
            _Pragma("unroll") \
            for (int nti = 0; nti < 8; nti++) { \
                uint32_t bb[2] = { (&bq[nti].x)[2 * kt], (&bq[nti].x)[2 * kt + 1] }; \
                mma16816(acc[mti][nti], ah[mti], bb); \
            } \
    } }

    G1_LOADA(0); G_STOREA(0);
    __syncthreads();

    const int NCH = 8;
    for (int kc = 0; kc < NCH; kc++) {
        int buf = kc & 1;
        if (kc + 1 < NCH) { G1_LOADA(kc + 1); }
        G1_COMPUTE(buf, kc);
        if (kc + 1 < NCH) { G_STOREA(buf ^ 1); }
        __syncthreads();
    }

    // ---- epilogue: stage 64x64 halves, scatter q/k/v ----
    float* stg = (float*)smem;
    for (int h = 0; h < 2; h++) {
        if (wn == h) {
            #pragma unroll
            for (int mti = 0; mti < 2; mti++)
                #pragma unroll
                for (int nti = 0; nti < 8; nti++) {
                    int r0 = wm * 32 + mti * 16 + (lane >> 2);
                    int c0 = nti * 8 + (lane & 3) * 2;
                    stg[r0 * 65 + c0]       = acc[mti][nti][0];
                    stg[r0 * 65 + c0 + 1]   = acc[mti][nti][1];
                    stg[(r0 + 8) * 65 + c0]     = acc[mti][nti][2];
                    stg[(r0 + 8) * 65 + c0 + 1] = acc[mti][nti][3];
                }
        }
        __syncthreads();
        int cc = tid & 63, qr = tid >> 6;
        int o = nb + h * 64 + cc;
        float bias = (o < 512) ? qk_b[o] : v_b[o - 512];
        #pragma unroll 4
        for (int i = 0; i < 32; i++) {
            int ml = qr + i * 2;
            float val = stg[ml * 65 + cc] + bias;
            int m = mb + ml;
            if (o < 512) {
                int bimg = m / PIX_PER_IMG;
                int hw = m - bimg * PIX_PER_IMG;
                int hh = hw / HWDIM, ww = hw - hh * HWDIM;
                int wi = bimg * 64 + (hh & 7) * 8 + (ww & 7);
                int n  = (hh >> 3) * 7 + (ww >> 3);
                if (o < 256)
                    g_q[(((size_t)wi * 8 + (o >> 5)) * 49 + n) * 32 + (o & 31)] = val * QSCALE;
                else {
                    int q2 = o - 256;
                    g_k[(((size_t)wi * 8 + (q2 >> 5)) * 49 + n) * 32 + (q2 & 31)] = val;
                }
            } else {
                g_v[(size_t)m * DE + (o - 512)] = val;
            }
        }
        __syncthreads();
    }
#undef G1_LOADA
#undef G1_COMPUTE
}

// ================= attention: one CTA per (window, head), vectorized LDS =================
__global__ __launch_bounds__(128) void attn_kernel(const float* __restrict__ rpb) {
    int head = blockIdx.x;
    int wi   = blockIdx.y;
    int wp   = wi & 63;
    int bimg = wi >> 6;
    int tid  = threadIdx.x;

    __shared__ float Qs[49][36];       // padded for float4
    __shared__ float Ks[49][36];
    __shared__ float Vs[49][64];
    __shared__ float Ss[49 * 49];
    __shared__ float rpbs[169];

    const float* qbase = g_q + ((size_t)wi * 8 + head) * 49 * 32;
    const float* kbase = g_k + ((size_t)wi * 8 + head) * 49 * 32;

    for (int i = tid; i < 49 * 32; i += 128) {
        Qs[i >> 5][i & 31] = qbase[i];
        Ks[i >> 5][i & 31] = kbase[i];
    }
    for (int i = tid; i < 169; i += 128)
        rpbs[i] = rpb[((size_t)wp * 169 + i) * 8 + head];
    for (int i = tid; i < 49 * 64; i += 128) {
        int n = i >> 6, vh = i & 63;
        int hh = (n / 7) * 8 + (wp >> 3), ww = (n % 7) * 8 + (wp & 7);
        size_t pix = (size_t)bimg * PIX_PER_IMG + hh * HWDIM + ww;
        Vs[n][vh] = g_v[pix * DE + head * 64 + vh];
    }
    __syncthreads();

    // scores + bias (float4 dot products)
    for (int i = tid; i < 49 * 49; i += 128) {
        int n = i / 49, m = i % 49;
        const float4* qr = (const float4*)&Qs[n][0];
        const float4* kr = (const float4*)&Ks[m][0];
        float s = 0.f;
        #pragma unroll
        for (int d4 = 0; d4 < 8; d4++) {
            float4 qa = qr[d4];
            float4 kb = kr[d4];
            s += qa.x * kb.x + qa.y * kb.y + qa.z * kb.z + qa.w * kb.w;
        }
        int i1 = n / 7, j1 = n % 7, i2 = m / 7, j2 = m % 7;
        s += rpbs[(i1 - i2 + 6) * 13 + (j1 - j2 + 6)];
        Ss[i] = s;
    }
    __syncthreads();

    if (tid < 49) {
        float* row = Ss + tid * 49;
        float mx = -1e30f;
        #pragma unroll 7
        for (int m = 0; m < 49; m++) mx = fmaxf(mx, row[m]);
        float sum = 0.f;
        #pragma unroll 7
        for (int m = 0; m < 49; m++) { float e = __expf(row[m] - mx); row[m] = e; sum += e; }
        float inv = 1.0f / sum;
        #pragma unroll 7
        for (int m = 0; m < 49; m++) row[m] *= inv;
    }
    __syncthreads();

    // O = S @ V, float2 over vh pairs (lanes within a warp share n -> Ss broadcast)
    for (int i = tid; i < 49 * 32; i += 128) {
        int n = i >> 5, vp = (i & 31) * 2;
        float ox = 0.f, oy = 0.f;
        const float* srow = Ss + n * 49;
        #pragma unroll 7
        for (int m = 0; m < 49; m++) {
            float sv = srow[m];
            float2 v = *(const float2*)&Vs[m][vp];
            ox += sv * v.x;
            oy += sv * v.y;
        }
        int hh = (n / 7) * 8 + (wp >> 3), ww = (n % 7) * 8 + (wp & 7);
        size_t pix = (size_t)bimg * PIX_PER_IMG + hh * HWDIM + ww;
        float2* dst = (float2*)(g_v + pix * DE + head * 64 + vp);
        *dst = make_float2(ox, oy);
    }
}

// ================= post-LN stats over first 512 cols of g_v =================
__global__ __launch_bounds__(256) void ln2_stats_kernel() {
    int row = blockIdx.x * 8 + (threadIdx.x >> 5);
    int lane = threadIdx.x & 31;
    const float4* p = (const float4*)(g_v + (size_t)row * DE);
    float s = 0.f, ss = 0.f;
    #pragma unroll
    for (int j = 0; j < 4; j++) {
        float4 v = p[lane + 32 * j];
        s  += v.x + v.y + v.z + v.w;
        ss += v.x * v.x + v.y * v.y + v.z * v.z + v.w * v.w;
    }
    #pragma unroll
    for (int off = 16; off; off >>= 1) {
        s  += __shfl_down_sync(0xffffffffu, s, off);
        ss += __shfl_down_sync(0xffffffffu, ss, off);
    }
    if (lane == 0) {
        float mean = s * (1.0f / 512.0f);
        float var  = ss * (1.0f / 512.0f) - mean * mean;
        g_ln2m[row] = mean;
        g_ln2r[row] = rsqrtf(var + 1e-5f);
    }
}

// ================= GEMM2: CTA 64x128 (128 thr, 4 CTAs/SM), B direct =================
__global__ __launch_bounds__(128, 4) void gemm2_mma(
    const float* __restrict__ x,
    const float* __restrict__ proj_b,
    float* __restrict__ out)
{
    extern __shared__ char smem[];
    uint4* As = (uint4*)smem;

    const int tid = threadIdx.x, lane = tid & 31, wid = tid >> 5;
    const int wm = wid >> 1, wn = wid & 1;
    const int mb = blockIdx.x * 64, nb = blockIdx.y * 128;
    const int mtg0 = mb >> 4, ntg0 = nb >> 3;

    float acc[2][8][4];
    #pragma unroll
    for (int i = 0; i < 2; i++)
        #pragma unroll
        for (int j = 0; j < 8; j++)
            #pragma unroll
            for (int r = 0; r < 4; r++) acc[i][j][r] = 0.f;

    uint4 av[2];

#define G2_LOADA(KC) { \
    _Pragma("unroll") \
    for (int j = 0; j < 2; j++) { \
        int i = tid + j * 128; \
        int l = i & 31, mt = (i >> 5) & 3, ktl = i >> 7; \
        av[j] = g_a2[((size_t)(mtg0 + mt) * 64 + (KC) * 2 + ktl) * 32 + l]; \
    } }

#define G2_COMPUTE(BUF, KC) { \
    uint4 bq[8]; \
    _Pragma("unroll") \
    for (int nti = 0; nti < 8; nti++) \
        bq[nti] = g_b2p[((size_t)(ntg0 + wn * 8 + nti) * 32 + (KC)) * 32 + lane]; \
    _Pragma("unroll") \
    for (int kt = 0; kt < 2; kt++) { \
        uint32_t ah[2][4]; \
        _Pragma("unroll") \
        for (int mti = 0; mti < 2; mti++) \
            *(uint4*)ah[mti] = As[AS_IDX(BUF, kt, wm * 2 + mti) + lane]; \
        _Pragma("unroll") \
        for (int mti = 0; mti < 2; mti++) \
            _Pragma("unroll") \
            for (int nti = 0; nti < 8; nti++) { \
                uint32_t bb[2] = { (&bq[nti].x)[2 * kt], (&bq[nti].x)[2 * kt + 1] }; \
                mma16816(acc[mti][nti], ah[mti], bb); \
            } \
    } }

    G2_LOADA(0); G_STOREA(0);
    __syncthreads();

    const int NCH = 32;
    for (int kc = 0; kc < NCH; kc++) {
        int buf = kc & 1;
        if (kc + 1 < NCH) { G2_LOADA(kc + 1); }
        G2_COMPUTE(buf, kc);
        if (kc + 1 < NCH) { G_STOREA(buf ^ 1); }
        __syncthreads();
    }

    // ---- epilogue: +bias +residual, rolled coalesced writes ----
    float* stg = (float*)smem;
    const int ml = tid & 63;
    const int cq = tid >> 6;   // 0..1
    int m = mb + ml;
    int bimg = m / PIX_PER_IMG;
    int hw = m - bimg * PIX_PER_IMG;
    int hh = hw / HWDIM, ww = hw - hh * HWDIM;
    int h2 = hh + 2; if (h2 >= HWDIM) h2 -= HWDIM;
    int w2 = ww + 2; if (w2 >= HWDIM) w2 -= HWDIM;
    size_t inbase  = (size_t)bimg * C_IN * PIX_PER_IMG + hw;
    size_t outbase = (size_t)bimg * C_IN * PIX_PER_IMG + h2 * HWDIM + w2;

    for (int h = 0; h < 2; h++) {
        if (wn == h) {
            #pragma unroll
            for (int mti = 0; mti < 2; mti++)
                #pragma unroll
                for (int nti = 0; nti < 8; nti++) {
                    int r0 = wm * 32 + mti * 16 + (lane >> 2);
                    int c0 = nti * 8 + (lane & 3) * 2;
                    stg[r0 * 65 + c0]       = acc[mti][nti][0];
                    stg[r0 * 65 + c0 + 1]   = acc[mti][nti][1];
                    stg[(r0 + 8) * 65 + c0]     = acc[mti][nti][2];
                    stg[(r0 + 8) * 65 + c0 + 1] = acc[mti][nti][3];
                }
        }
        __syncthreads();
        #pragma unroll 4
        for (int i = 0; i < 32; i++) {
            int c = i * 2 + cq;
            int o = nb + h * 64 + c;
            float val = stg[ml * 65 + c] + proj_b[o] + x[inbase + (size_t)o * PIX_PER_IMG];
            out[outbase + (size_t)o * PIX_PER_IMG] = val;
        }
        __syncthreads();
    }
#undef G2_LOADA
#undef G2_COMPUTE
}

// ================= launch =================
extern "C" void kernel_launch(void* const* d_in, const int* in_sizes, int n_in,
                              void* d_out, int out_size) {
    const float* x      = (const float*)d_in[0];
    const float* pre_g  = (const float*)d_in[1];
    const float* pre_b  = (const float*)d_in[2];
    const float* post_g = (const float*)d_in[3];
    const float* post_b = (const float*)d_in[4];
    const float* qk_w   = (const float*)d_in[5];
    const float* qk_b   = (const float*)d_in[6];
    const float* v_w    = (const float*)d_in[7];
    const float* v_b    = (const float*)d_in[8];
    const float* proj_w = (const float*)d_in[9];
    const float* proj_b = (const float*)d_in[10];
    const float* rpb    = (const float*)d_in[11];
    float* out = (float*)d_out;

    static int configured = 0;
    if (!configured) {
        cudaFuncSetAttribute(gemm1_mma, cudaFuncAttributeMaxDynamicSharedMemorySize, SMEM_BYTES);
        cudaFuncSetAttribute(gemm2_mma, cudaFuncAttributeMaxDynamicSharedMemorySize, SMEM_BYTES);
        configured = 1;
    }

    conv_w1<<<192, 256>>>(qk_w, v_w);
    conv_w2<<<128, 256>>>(proj_w);
    conv_a1<<<MT_TOT, 256>>>(x, pre_g, pre_b);
    gemm1_mma<<<dim3(12, NPIX / 64), 128, SMEM_BYTES>>>(qk_b, v_b);
    attn_kernel<<<dim3(NH, NWIN), 128>>>(rpb);
    ln2_stats_kernel<<<NPIX / 8, 256>>>();
    conv_a2<<<MT_TOT, 256>>>(post_g, post_b);
    gemm2_mma<<<dim3(NPIX / 64, 2), 128, SMEM_BYTES>>>(x, proj_b, out);
}

// round 16
// speedup vs baseline: 1.2209x; 1.0511x over previous
#include <cuda_runtime.h>
#include <cuda_fp16.h>
#include <cstdint>
#include <math.h>

// ---------------- problem constants ----------------
#define B_IMG  32
#define C_IN   256
#define HWDIM  56
#define PIX_PER_IMG (HWDIM*HWDIM)      // 3136
#define NPIX   (B_IMG*PIX_PER_IMG)     // 100352
#define N_TOK  49
#define NH     8
#define DH     32
#define DE     1024
#define VA     512                      // attn-channel width of g_v rows
#define NWIN   (B_IMG*64)              // 2048
#define QSCALE 0.17677669529663687f
#define MT_TOT (NPIX/16)               // 6272

// ---------------- scratch ----------------
__device__ float g_ln2m[NPIX];
__device__ float g_ln2r[NPIX];
__device__ float g_q[NWIN*NH*N_TOK*DH];
__device__ float g_k[NWIN*NH*N_TOK*DH];
__device__ float g_v[(size_t)NPIX*VA];         // RASTER rows: [pixel][512] (attn half only)

// fragment-layout fp16 buffers
__device__ uint4 g_a1[(size_t)MT_TOT*16*32];   // [mt][kt16][lane]
__device__ uint4 g_b1p[192*8*32];              // [nt][kc32][lane] kt-paired
__device__ uint4 g_a2[(size_t)MT_TOT*64*32];   // [mt][kt64][lane]
__device__ uint4 g_b2p[32*32*32];              // [nt][kc32][lane] kt-paired

__device__ __forceinline__ float gelu_exact(float x) {
    return 0.5f * x * (1.0f + erff(x * 0.7071067811865476f));
}

// ---------------- mma helpers ----------------
__device__ __forceinline__ void mma16816(float* c, const uint32_t* a, const uint32_t* b) {
    asm volatile("mma.sync.aligned.m16n8k16.row.col.f32.f16.f16.f32 "
        "{%0,%1,%2,%3}, {%4,%5,%6,%7}, {%8,%9}, {%0,%1,%2,%3};"
        : "+f"(c[0]), "+f"(c[1]), "+f"(c[2]), "+f"(c[3])
        : "r"(a[0]), "r"(a[1]), "r"(a[2]), "r"(a[3]), "r"(b[0]), "r"(b[1]));
}
__device__ __forceinline__ uint32_t packh2(__half a, __half b) {
    __half2 t = __halves2half2(a, b);
    return *reinterpret_cast<uint32_t*>(&t);
}
__device__ __forceinline__ uint32_t roundh2(float v0, float v1) {
    return packh2(__float2half_rn(v0), __float2half_rn(v1));
}

// smem layout (dynamic): A double buffer 8KB; epilogue staging reuses (16.6KB)
//  As (uint4): [stage2][kt2][mt4][lane32]
#define AS_IDX(s,kt,mt)  ((((s)*2+(kt))*4+(mt))*32)
#define SMEM_BYTES 16896

// ================= converters =================
__global__ __launch_bounds__(256) void conv_w1(const float* __restrict__ qk_w,
                                               const float* __restrict__ v_w) {
    int t = blockIdx.x * 256 + threadIdx.x;     // 0..49151
    int lane = t & 31;
    int kc = (t >> 5) & 7;
    int nt = t >> 8;
    int n = nt * 8 + (lane >> 2);
    int k = kc * 32 + (lane & 3) * 2;
    const float* wr = (n < 512) ? qk_w + (size_t)n * 256 : v_w + (size_t)(n - 512) * 256;
    uint4 o;
    o.x = roundh2(wr[k],      wr[k + 1]);
    o.y = roundh2(wr[k + 8],  wr[k + 9]);
    o.z = roundh2(wr[k + 16], wr[k + 17]);
    o.w = roundh2(wr[k + 24], wr[k + 25]);
    g_b1p[t] = o;
}

__global__ __launch_bounds__(256) void conv_w2(const float* __restrict__ proj_w) {
    int t = blockIdx.x * 256 + threadIdx.x;     // 0..32767
    int lane = t & 31;
    int kc = (t >> 5) & 31;
    int nt = t >> 10;
    int n = nt * 8 + (lane >> 2);
    int k = kc * 32 + (lane & 3) * 2;
    const float* wr = proj_w + (size_t)n * 1024;
    uint4 o;
    o.x = roundh2(wr[k],      wr[k + 1]);
    o.y = roundh2(wr[k + 8],  wr[k + 9]);
    o.z = roundh2(wr[k + 16], wr[k + 17]);
    o.w = roundh2(wr[k + 24], wr[k + 25]);
    g_b2p[t] = o;
}

// ================= conv_a1: x -> LN (stats in-block) -> A1 frags (fp16) =================
__global__ __launch_bounds__(256) void conv_a1(const float* __restrict__ x,
                                               const float* __restrict__ pre_g,
                                               const float* __restrict__ pre_b) {
    int mt = blockIdx.x;
    int w = threadIdx.x >> 5, lane = threadIdx.x & 31;
    int rl0 = lane >> 2, rl1 = rl0 + 8;
    int r0 = mt * 16 + rl0, r1 = r0 + 8;
    int img = r0 / PIX_PER_IMG;
    int hw0 = r0 - img * PIX_PER_IMG;
    int hw1 = hw0 + 8;
    const float* xb = x + (size_t)img * C_IN * PIX_PER_IMG;

    float v0[8], v1[8];
    #pragma unroll
    for (int kk = 0; kk < 2; kk++) {
        int kt = w + kk * 8;
        int c = kt * 16 + (lane & 3) * 2;
        #pragma unroll
        for (int p2 = 0; p2 < 2; p2++) {
            int cc = c + p2 * 8;
            int ib = kk * 4 + p2 * 2;
            v0[ib + 0] = xb[(size_t)cc * PIX_PER_IMG + hw0];
            v0[ib + 1] = xb[(size_t)(cc + 1) * PIX_PER_IMG + hw0];
            v1[ib + 0] = xb[(size_t)cc * PIX_PER_IMG + hw1];
            v1[ib + 1] = xb[(size_t)(cc + 1) * PIX_PER_IMG + hw1];
        }
    }

    float s0 = 0.f, ss0 = 0.f, s1 = 0.f, ss1 = 0.f;
    #pragma unroll
    for (int i = 0; i < 8; i++) {
        s0 += v0[i]; ss0 += v0[i] * v0[i];
        s1 += v1[i]; ss1 += v1[i] * v1[i];
    }
    #pragma unroll
    for (int off = 1; off <= 2; off <<= 1) {
        s0  += __shfl_xor_sync(0xffffffffu, s0, off);
        ss0 += __shfl_xor_sync(0xffffffffu, ss0, off);
        s1  += __shfl_xor_sync(0xffffffffu, s1, off);
        ss1 += __shfl_xor_sync(0xffffffffu, ss1, off);
    }
    __shared__ float shs[16][8], shss[16][8];
    if ((lane & 3) == 0) {
        shs[rl0][w] = s0;  shss[rl0][w] = ss0;
        shs[rl1][w] = s1;  shss[rl1][w] = ss1;
    }
    __syncthreads();
    float S0 = 0.f, SS0 = 0.f, S1 = 0.f, SS1 = 0.f;
    #pragma unroll
    for (int q = 0; q < 8; q++) {
        S0 += shs[rl0][q]; SS0 += shss[rl0][q];
        S1 += shs[rl1][q]; SS1 += shss[rl1][q];
    }
    float mu0 = S0 * (1.0f / 256.0f);
    float rs0 = rsqrtf(SS0 * (1.0f / 256.0f) - mu0 * mu0 + 1e-5f);
    float mu1 = S1 * (1.0f / 256.0f);
    float rs1 = rsqrtf(SS1 * (1.0f / 256.0f) - mu1 * mu1 + 1e-5f);

    #pragma unroll
    for (int kk = 0; kk < 2; kk++) {
        int kt = w + kk * 8;
        int c = kt * 16 + (lane & 3) * 2;
        uint4 hv;
        #pragma unroll
        for (int p2 = 0; p2 < 2; p2++) {
            int cc = c + p2 * 8;
            int ib = kk * 4 + p2 * 2;
            float g0 = pre_g[cc], b0 = pre_b[cc], g1 = pre_g[cc + 1], b1 = pre_b[cc + 1];
            float t00 = (v0[ib + 0] - mu0) * rs0 * g0 + b0;
            float t01 = (v0[ib + 1] - mu0) * rs0 * g1 + b1;
            float t10 = (v1[ib + 0] - mu1) * rs1 * g0 + b0;
            float t11 = (v1[ib + 1] - mu1) * rs1 * g1 + b1;
            (&hv.x)[2 * p2]     = roundh2(t00, t01);
            (&hv.x)[2 * p2 + 1] = roundh2(t10, t11);
        }
        g_a1[((size_t)mt * 16 + kt) * 32 + lane] = hv;
    }
}

// ================= conv_a2: gelu(postLN(g_v attn half)) -> A2 frags kts 0..31 =================
__global__ __launch_bounds__(256) void conv_a2(const float* __restrict__ post_g,
                                               const float* __restrict__ post_b) {
    int mt = blockIdx.x;
    int w = threadIdx.x >> 5, lane = threadIdx.x & 31;
    int r0 = mt * 16 + (lane >> 2), r1 = r0 + 8;
    const float* gv0 = g_v + (size_t)r0 * VA;
    const float* gv1 = g_v + (size_t)r1 * VA;
    float mu0 = g_ln2m[r0], rs0 = g_ln2r[r0];
    float mu1 = g_ln2m[r1], rs1 = g_ln2r[r1];
    #pragma unroll
    for (int kk = 0; kk < 4; kk++) {
        int kt = w + kk * 8;               // 0..31
        int c = kt * 16 + (lane & 3) * 2;
        uint4 hv;
        #pragma unroll
        for (int p2 = 0; p2 < 2; p2++) {
            int cc = c + p2 * 8;
            float2 f0 = *(const float2*)(gv0 + cc);
            float2 f1 = *(const float2*)(gv1 + cc);
            float g0 = post_g[cc], b0 = post_b[cc];
            float g1 = post_g[cc + 1], b1 = post_b[cc + 1];
            float t00 = (f0.x - mu0) * rs0 * g0 + b0;
            float t01 = (f0.y - mu0) * rs0 * g1 + b1;
            float t10 = (f1.x - mu1) * rs1 * g0 + b0;
            float t11 = (f1.y - mu1) * rs1 * g1 + b1;
            t00 = gelu_exact(t00); t01 = gelu_exact(t01);
            t10 = gelu_exact(t10); t11 = gelu_exact(t11);
            (&hv.x)[2 * p2]     = roundh2(t00, t01);
            (&hv.x)[2 * p2 + 1] = roundh2(t10, t11);
        }
        g_a2[((size_t)mt * 64 + kt) * 32 + lane] = hv;
    }
}

// ================= GEMM1: CTA 64x128 (128 thr, 4 CTAs/SM), B direct =================
// epilogue: o<512 -> q/k scatter; o>=512 -> gelu(val+v_b) -> g_a2 frags (kts 32..63)
__global__ __launch_bounds__(128, 4) void gemm1_mma(
    const float* __restrict__ qk_b, const float* __restrict__ v_b)
{
    extern __shared__ char smem[];
    uint4* As = (uint4*)smem;

    const int tid = threadIdx.x, lane = tid & 31, wid = tid >> 5;
    const int wm = wid >> 1, wn = wid & 1;
    const int mb = blockIdx.y * 64, nb = blockIdx.x * 128;
    const int mtg0 = mb >> 4, ntg0 = nb >> 3;

    float acc[2][8][4];
    #pragma unroll
    for (int i = 0; i < 2; i++)
        #pragma unroll
        for (int j = 0; j < 8; j++)
            #pragma unroll
            for (int r = 0; r < 4; r++) acc[i][j][r] = 0.f;

    uint4 av[2];

#define G1_LOADA(KC) { \
    _Pragma("unroll") \
    for (int j = 0; j < 2; j++) { \
        int i = tid + j * 128; \
        int l = i & 31, mt = (i >> 5) & 3, ktl = i >> 7; \
        av[j] = g_a1[((size_t)(mtg0 + mt) * 16 + (KC) * 2 + ktl) * 32 + l]; \
    } }

#define G_STOREA(ST) { \
    _Pragma("unroll") \
    for (int j = 0; j < 2; j++) { \
        int i = tid + j * 128; \
        int l = i & 31, mt = (i >> 5) & 3, ktl = i >> 7; \
        As[AS_IDX(ST, ktl, mt) + l] = av[j]; \
    } }

#define G1_COMPUTE(BUF, KC) { \
    uint4 bq[8]; \
    _Pragma("unroll") \
    for (int nti = 0; nti < 8; nti++) \
        bq[nti] = g_b1p[((size_t)(ntg0 + wn * 8 + nti) * 8 + (KC)) * 32 + lane]; \
    _Pragma("unroll") \
    for (int kt = 0; kt < 2; kt++) { \
        uint32_t ah[2][4]; \
        _Pragma("unroll") \
        for (int mti = 0; mti < 2; mti++) \
            *(uint4*)ah[mti] = As[AS_IDX(BUF, kt, wm * 2 + mti) + lane]; \
        _Pragma("unroll") \
        for (int mti = 0; mti < 2; mti++) \
            _Pragma("unroll") \
            for (int nti = 0; nti < 8; nti++) { \
                uint32_t bb[2] = { (&bq[nti].x)[2 * kt], (&bq[nti].x)[2 * kt + 1] }; \
                mma16816(acc[mti][nti], ah[mti], bb); \
            } \
    } }

    G1_LOADA(0); G_STOREA(0);
    __syncthreads();

    const int NCH = 8;
    for (int kc = 0; kc < NCH; kc++) {
        int buf = kc & 1;
        if (kc + 1 < NCH) { G1_LOADA(kc + 1); }
        G1_COMPUTE(buf, kc);
        if (kc + 1 < NCH) { G_STOREA(buf ^ 1); }
        __syncthreads();
    }

    // ---- epilogue ----
    float* stg = (float*)smem;
    for (int h = 0; h < 2; h++) {
        if (wn == h) {
            #pragma unroll
            for (int mti = 0; mti < 2; mti++)
                #pragma unroll
                for (int nti = 0; nti < 8; nti++) {
                    int r0 = wm * 32 + mti * 16 + (lane >> 2);
                    int c0 = nti * 8 + (lane & 3) * 2;
                    stg[r0 * 65 + c0]       = acc[mti][nti][0];
                    stg[r0 * 65 + c0 + 1]   = acc[mti][nti][1];
                    stg[(r0 + 8) * 65 + c0]     = acc[mti][nti][2];
                    stg[(r0 + 8) * 65 + c0 + 1] = acc[mti][nti][3];
                }
        }
        __syncthreads();
        int ob = nb + h * 64;
        if (ob < 512) {
            // q/k scatter
            int cc = tid & 63, qr = tid >> 6;
            int o = ob + cc;
            float bias = qk_b[o];
            #pragma unroll 4
            for (int i = 0; i < 32; i++) {
                int ml = qr + i * 2;
                float val = stg[ml * 65 + cc] + bias;
                int m = mb + ml;
                int bimg = m / PIX_PER_IMG;
                int hw = m - bimg * PIX_PER_IMG;
                int hh = hw / HWDIM, ww = hw - hh * HWDIM;
                int wi = bimg * 64 + (hh & 7) * 8 + (ww & 7);
                int n  = (hh >> 3) * 7 + (ww >> 3);
                if (o < 256)
                    g_q[(((size_t)wi * 8 + (o >> 5)) * 49 + n) * 32 + (o & 31)] = val * QSCALE;
                else {
                    int q2 = o - 256;
                    g_k[(((size_t)wi * 8 + (q2 >> 5)) * 49 + n) * 32 + (q2 & 31)] = val;
                }
            }
        } else if (ob < 1024) {
            // v_attn: +v_b -> g_v (512-wide rows)
            int cc = tid & 63, qr = tid >> 6;
            int o = ob + cc;
            int vo = o - 512;
            float bias = v_b[vo];
            #pragma unroll 4
            for (int i = 0; i < 32; i++) {
                int ml = qr + i * 2;
                float val = stg[ml * 65 + cc] + bias;
                g_v[(size_t)(mb + ml) * VA + vo] = val;
            }
        } else {
            // v_idle: gelu(val + v_b) -> g_a2 fragments (kts 32..63)
            int ln = tid & 31;
            int p = tid >> 2 >> 3;      // tid>>5: 0..3
            int ktbase = ob >> 4;       // 64..; g_a2 kt index = (o>>4) since xg col = o... careful:
            // xg col for v_idle o is (o - 512) + 512 = o - 512 + 512? xg = [postLN(attn) 0..511 | v_idle 0..511]
            // v_idle occupies xg cols 512..1023 -> kt = 32 + (vo>>4) = 32 + ((ob-1024+...)>>4)
            int ktb = 32 + ((ob - 1024) >> 4) + 32;  // = (ob>>4) - 64 + 64 ... compute directly below
            (void)ktb; (void)ktbase;
            #pragma unroll
            for (int j = 0; j < 4; j++) {
                int pidx = p + j * 4;
                int mtl = pidx & 3, ktl = pidx >> 2;
                int r0 = mtl * 16 + (ln >> 2), r1 = r0 + 8;
                int c0 = ktl * 16 + (ln & 3) * 2;
                int vo0 = (ob - 512) + c0;          // v index 512..1023 region -> xg col = vo0 + ... 
                float b0 = v_b[vo0], b1 = v_b[vo0 + 1];
                float b8 = v_b[vo0 + 8], b9 = v_b[vo0 + 9];
                uint4 hv;
                float t00 = gelu_exact(stg[r0 * 65 + c0] + b0);
                float t01 = gelu_exact(stg[r0 * 65 + c0 + 1] + b1);
                float t10 = gelu_exact(stg[r1 * 65 + c0] + b0);
                float t11 = gelu_exact(stg[r1 * 65 + c0 + 1] + b1);
                hv.x = roundh2(t00, t01);
                hv.y = roundh2(t10, t11);
                t00 = gelu_exact(stg[r0 * 65 + c0 + 8] + b8);
                t01 = gelu_exact(stg[r0 * 65 + c0 + 9] + b9);
                t10 = gelu_exact(stg[r1 * 65 + c0 + 8] + b8);
                t11 = gelu_exact(stg[r1 * 65 + c0 + 9] + b9);
                hv.z = roundh2(t00, t01);
                hv.w = roundh2(t10, t11);
                // xg col = 512 + (vo0 ... ) -> kt_global = (512 + (ob-512) + ktl*16) >> 4 = (ob>>4) + ktl... 
                int ktg = (ob >> 4) + ktl - 32;     // ob in [1024,1536): (ob>>4) in [64,96) -> ktg in [32,64)
                g_a2[((size_t)(mtg0 + mtl) * 64 + ktg) * 32 + ln] = hv;
            }
        }
        __syncthreads();
    }
#undef G1_LOADA
#undef G1_COMPUTE
}

// ================= attention: one CTA per (window, head), vectorized LDS =================
__global__ __launch_bounds__(128) void attn_kernel(const float* __restrict__ rpb) {
    int head = blockIdx.x;
    int wi   = blockIdx.y;
    int wp   = wi & 63;
    int bimg = wi >> 6;
    int tid  = threadIdx.x;

    __shared__ float Qs[49][36];       // padded for float4
    __shared__ float Ks[49][36];
    __shared__ float Vs[49][64];
    __shared__ float Ss[49 * 49];
    __shared__ float rpbs[169];

    const float4* qbase = (const float4*)(g_q + ((size_t)wi * 8 + head) * 49 * 32);
    const float4* kbase = (const float4*)(g_k + ((size_t)wi * 8 + head) * 49 * 32);

    for (int i = tid; i < 49 * 8; i += 128) {
        int n = i >> 3, d4 = i & 7;
        *(float4*)&Qs[n][d4 * 4] = qbase[i];
        *(float4*)&Ks[n][d4 * 4] = kbase[i];
    }
    for (int i = tid; i < 169; i += 128)
        rpbs[i] = rpb[((size_t)wp * 169 + i) * 8 + head];
    for (int i = tid; i < 49 * 16; i += 128) {
        int n = i >> 4, v4 = (i & 15) * 4;
        int hh = (n / 7) * 8 + (wp >> 3), ww = (n % 7) * 8 + (wp & 7);
        size_t pix = (size_t)bimg * PIX_PER_IMG + hh * HWDIM + ww;
        *(float4*)&Vs[n][v4] = *(const float4*)(g_v + pix * VA + head * 64 + v4);
    }
    __syncthreads();

    // scores + bias (float4 dot products)
    for (int i = tid; i < 49 * 49; i += 128) {
        int n = i / 49, m = i % 49;
        const float4* qr = (const float4*)&Qs[n][0];
        const float4* kr = (const float4*)&Ks[m][0];
        float s = 0.f;
        #pragma unroll
        for (int d4 = 0; d4 < 8; d4++) {
            float4 qa = qr[d4];
            float4 kb = kr[d4];
            s += qa.x * kb.x + qa.y * kb.y + qa.z * kb.z + qa.w * kb.w;
        }
        int i1 = n / 7, j1 = n % 7, i2 = m / 7, j2 = m % 7;
        s += rpbs[(i1 - i2 + 6) * 13 + (j1 - j2 + 6)];
        Ss[i] = s;
    }
    __syncthreads();

    if (tid < 49) {
        float* row = Ss + tid * 49;
        float mx = -1e30f;
        #pragma unroll 7
        for (int m = 0; m < 49; m++) mx = fmaxf(mx, row[m]);
        float sum = 0.f;
        #pragma unroll 7
        for (int m = 0; m < 49; m++) { float e = __expf(row[m] - mx); row[m] = e; sum += e; }
        float inv = 1.0f / sum;
        #pragma unroll 7
        for (int m = 0; m < 49; m++) row[m] *= inv;
    }
    __syncthreads();

    // O = S @ V, float2 over vh pairs
    for (int i = tid; i < 49 * 32; i += 128) {
        int n = i >> 5, vp = (i & 31) * 2;
        float ox = 0.f, oy = 0.f;
        const float* srow = Ss + n * 49;
        #pragma unroll 7
        for (int m = 0; m < 49; m++) {
            float sv = srow[m];
            float2 v = *(const float2*)&Vs[m][vp];
            ox += sv * v.x;
            oy += sv * v.y;
        }
        int hh = (n / 7) * 8 + (wp >> 3), ww = (n % 7) * 8 + (wp & 7);
        size_t pix = (size_t)bimg * PIX_PER_IMG + hh * HWDIM + ww;
        float2* dst = (float2*)(g_v + pix * VA + head * 64 + vp);
        *dst = make_float2(ox, oy);
    }
}

// ================= post-LN stats over g_v rows (512 cols) =================
__global__ __launch_bounds__(256) void ln2_stats_kernel() {
    int row = blockIdx.x * 8 + (threadIdx.x >> 5);
    int lane = threadIdx.x & 31;
    const float4* p = (const float4*)(g_v + (size_t)row * VA);
    float s = 0.f, ss = 0.f;
    #pragma unroll
    for (int j = 0; j < 4; j++) {
        float4 v = p[lane + 32 * j];
        s  += v.x + v.y + v.z + v.w;
        ss += v.x * v.x + v.y * v.y + v.z * v.z + v.w * v.w;
    }
    #pragma unroll
    for (int off = 16; off; off >>= 1) {
        s  += __shfl_down_sync(0xffffffffu, s, off);
        ss += __shfl_down_sync(0xffffffffu, ss, off);
    }
    if (lane == 0) {
        float mean = s * (1.0f / 512.0f);
        float var  = ss * (1.0f / 512.0f) - mean * mean;
        g_ln2m[row] = mean;
        g_ln2r[row] = rsqrtf(var + 1e-5f);
    }
}

// ================= GEMM2: CTA 64x128 (128 thr, 4 CTAs/SM), B direct =================
__global__ __launch_bounds__(128, 4) void gemm2_mma(
    const float* __restrict__ x,
    const float* __restrict__ proj_b,
    float* __restrict__ out)
{
    extern __shared__ char smem[];
    uint4* As = (uint4*)smem;

    const int tid = threadIdx.x, lane = tid & 31, wid = tid >> 5;
    const int wm = wid >> 1, wn = wid & 1;
    const int mb = blockIdx.x * 64, nb = blockIdx.y * 128;
    const int mtg0 = mb >> 4, ntg0 = nb >> 3;

    float acc[2][8][4];
    #pragma unroll
    for (int i = 0; i < 2; i++)
        #pragma unroll
        for (int j = 0; j < 8; j++)
            #pragma unroll
            for (int r = 0; r < 4; r++) acc[i][j][r] = 0.f;

    uint4 av[2];

#define G2_LOADA(KC) { \
    _Pragma("unroll") \
    for (int j = 0; j < 2; j++) { \
        int i = tid + j * 128; \
        int l = i & 31, mt = (i >> 5) & 3, ktl = i >> 7; \
        av[j] = g_a2[((size_t)(mtg0 + mt) * 64 + (KC) * 2 + ktl) * 32 + l]; \
    } }

#define G2_COMPUTE(BUF, KC) { \
    uint4 bq[8]; \
    _Pragma("unroll") \
    for (int nti = 0; nti < 8; nti++) \
        bq[nti] = g_b2p[((size_t)(ntg0 + wn * 8 + nti) * 32 + (KC)) * 32 + lane]; \
    _Pragma("unroll") \
    for (int kt = 0; kt < 2; kt++) { \
        uint32_t ah[2][4]; \
        _Pragma("unroll") \
        for (int mti = 0; mti < 2; mti++) \
            *(uint4*)ah[mti] = As[AS_IDX(BUF, kt, wm * 2 + mti) + lane]; \
        _Pragma("unroll") \
        for (int mti = 0; mti < 2; mti++) \
            _Pragma("unroll") \
            for (int nti = 0; nti < 8; nti++) { \
                uint32_t bb[2] = { (&bq[nti].x)[2 * kt], (&bq[nti].x)[2 * kt + 1] }; \
                mma16816(acc[mti][nti], ah[mti], bb); \
            } \
    } }

    G2_LOADA(0); G_STOREA(0);
    __syncthreads();

    const int NCH = 32;
    for (int kc = 0; kc < NCH; kc++) {
        int buf = kc & 1;
        if (kc + 1 < NCH) { G2_LOADA(kc + 1); }
        G2_COMPUTE(buf, kc);
        if (kc + 1 < NCH) { G_STOREA(buf ^ 1); }
        __syncthreads();
    }

    // ---- epilogue: +bias +residual, rolled coalesced writes ----
    float* stg = (float*)smem;
    const int ml = tid & 63;
    const int cq = tid >> 6;   // 0..1
    int m = mb + ml;
    int bimg = m / PIX_PER_IMG;
    int hw = m - bimg * PIX_PER_IMG;
    int hh = hw / HWDIM, ww = hw - hh * HWDIM;
    int h2 = hh + 2; if (h2 >= HWDIM) h2 -= HWDIM;
    int w2 = ww + 2; if (w2 >= HWDIM) w2 -= HWDIM;
    size_t inbase  = (size_t)bimg * C_IN * PIX_PER_IMG + hw;
    size_t outbase = (size_t)bimg * C_IN * PIX_PER_IMG + h2 * HWDIM + w2;

    for (int h = 0; h < 2; h++) {
        if (wn == h) {
            #pragma unroll
            for (int mti = 0; mti < 2; mti++)
                #pragma unroll
                for (int nti = 0; nti < 8; nti++) {
                    int r0 = wm * 32 + mti * 16 + (lane >> 2);
                    int c0 = nti * 8 + (lane & 3) * 2;
                    stg[r0 * 65 + c0]       = acc[mti][nti][0];
                    stg[r0 * 65 + c0 + 1]   = acc[mti][nti][1];
                    stg[(r0 + 8) * 65 + c0]     = acc[mti][nti][2];
                    stg[(r0 + 8) * 65 + c0 + 1] = acc[mti][nti][3];
                }
        }
        __syncthreads();
        #pragma unroll 4
        for (int i = 0; i < 32; i++) {
            int c = i * 2 + cq;
            int o = nb + h * 64 + c;
            float val = stg[ml * 65 + c] + proj_b[o] + x[inbase + (size_t)o * PIX_PER_IMG];
            out[outbase + (size_t)o * PIX_PER_IMG] = val;
        }
        __syncthreads();
    }
#undef G2_LOADA
#undef G2_COMPUTE
}

// ================= launch =================
extern "C" void kernel_launch(void* const* d_in, const int* in_sizes, int n_in,
                              void* d_out, int out_size) {
    const float* x      = (const float*)d_in[0];
    const float* pre_g  = (const float*)d_in[1];
    const float* pre_b  = (const float*)d_in[2];
    const float* post_g = (const float*)d_in[3];
    const float* post_b = (const float*)d_in[4];
    const float* qk_w   = (const float*)d_in[5];
    const float* qk_b   = (const float*)d_in[6];
    const float* v_w    = (const float*)d_in[7];
    const float* v_b    = (const float*)d_in[8];
    const float* proj_w = (const float*)d_in[9];
    const float* proj_b = (const float*)d_in[10];
    const float* rpb    = (const float*)d_in[11];
    float* out = (float*)d_out;

    static int configured = 0;
    if (!configured) {
        cudaFuncSetAttribute(gemm1_mma, cudaFuncAttributeMaxDynamicSharedMemorySize, SMEM_BYTES);
        cudaFuncSetAttribute(gemm2_mma, cudaFuncAttributeMaxDynamicSharedMemorySize, SMEM_BYTES);
        configured = 1;
    }

    conv_w1<<<192, 256>>>(qk_w, v_w);
    conv_w2<<<128, 256>>>(proj_w);
    conv_a1<<<MT_TOT, 256>>>(x, pre_g, pre_b);
    gemm1_mma<<<dim3(12, NPIX / 64), 128, SMEM_BYTES>>>(qk_b, v_b);
    attn_kernel<<<dim3(NH, NWIN), 128>>>(rpb);
    ln2_stats_kernel<<<NPIX / 8, 256>>>();
    conv_a2<<<MT_TOT, 256>>>(post_g, post_b);
    gemm2_mma<<<dim3(NPIX / 64, 2), 128, SMEM_BYTES>>>(x, proj_b, out);
}